// round 1
// baseline (speedup 1.0000x reference)
#include <cuda_runtime.h>
#include <math.h>

// ---------------- problem constants ----------------
#define LSEQ   4096
#define HDIM   2048
#define NKH    16
#define NVH    32
#define DKD    128
#define DVD    128
#define QKVZ_N 12288            // 2*KEY_DIM + 2*VAL_DIM
#define MIXED_N 8192            // 2*KEY_DIM + VAL_DIM
#define KEY_DIM 2048
#define VAL_DIM 4096

// ---------------- scratch (static device memory; no allocs allowed) --------
__device__ float g_qkvz [LSEQ * QKVZ_N];   // 201 MB
__device__ float g_ba   [LSEQ * 64];
__device__ float g_mixed[LSEQ * MIXED_N];  // 128 MB (post conv+silu)
__device__ float g_qn   [LSEQ * NKH * DKD];
__device__ float g_kn   [LSEQ * NKH * DKD];
__device__ float g_gv   [LSEQ * NVH];
__device__ float g_bv   [LSEQ * NVH];
__device__ float g_core [LSEQ * NVH * DVD];
__device__ float g_gated[LSEQ * NVH * DVD];

// ---------------- fp32 SGEMM:  C[M,N] = A[M,K] * B[N,K]^T  -----------------
// A row-major [M,K], B row-major [N,K]; M%128==0, N%128==0, K%16==0 assumed.
#define BM 128
#define BN 128
#define BK 16
__global__ __launch_bounds__(256) void sgemm_nt(
    const float* __restrict__ A, const float* __restrict__ B,
    float* __restrict__ C, int M, int N, int Kdim)
{
    __shared__ __align__(16) float As[BK][BM];
    __shared__ __align__(16) float Bs[BK][BN];

    const int tid = threadIdx.x;
    const int bn  = blockIdx.x;
    const int bm  = blockIdx.y;

    const float* Ab = A + (size_t)bm * BM * Kdim;
    const float* Bb = B + (size_t)bn * BN * Kdim;

    const int tm = (tid >> 4) << 3;   // 0..120
    const int tn = (tid & 15) << 3;   // 0..120

    float acc[8][8];
#pragma unroll
    for (int i = 0; i < 8; i++)
#pragma unroll
        for (int j = 0; j < 8; j++) acc[i][j] = 0.f;

    for (int kt = 0; kt < Kdim; kt += BK) {
        // each thread loads 2 float4 of A and 2 float4 of B (128x16 tile each)
#pragma unroll
        for (int j = 0; j < 2; j++) {
            int idx = tid * 2 + j;        // 0..511
            int row = idx >> 2;           // 0..127
            int kc  = idx & 3;            // 0..3 (float4 within the 16-wide K)
            float4 av = *(const float4*)(Ab + (size_t)row * Kdim + kt + kc * 4);
            As[kc*4+0][row] = av.x; As[kc*4+1][row] = av.y;
            As[kc*4+2][row] = av.z; As[kc*4+3][row] = av.w;
            float4 bv = *(const float4*)(Bb + (size_t)row * Kdim + kt + kc * 4);
            Bs[kc*4+0][row] = bv.x; Bs[kc*4+1][row] = bv.y;
            Bs[kc*4+2][row] = bv.z; Bs[kc*4+3][row] = bv.w;
        }
        __syncthreads();

#pragma unroll
        for (int kk = 0; kk < BK; kk++) {
            float a[8], b[8];
            *(float4*)&a[0] = *(const float4*)&As[kk][tm];
            *(float4*)&a[4] = *(const float4*)&As[kk][tm + 4];
            *(float4*)&b[0] = *(const float4*)&Bs[kk][tn];
            *(float4*)&b[4] = *(const float4*)&Bs[kk][tn + 4];
#pragma unroll
            for (int i = 0; i < 8; i++)
#pragma unroll
                for (int j = 0; j < 8; j++)
                    acc[i][j] += a[i] * b[j];
        }
        __syncthreads();
    }

    float* Cb = C + (size_t)(bm * BM + tm) * N + bn * BN + tn;
#pragma unroll
    for (int i = 0; i < 8; i++) {
        *(float4*)(Cb + (size_t)i * N)     = make_float4(acc[i][0], acc[i][1], acc[i][2], acc[i][3]);
        *(float4*)(Cb + (size_t)i * N + 4) = make_float4(acc[i][4], acc[i][5], acc[i][6], acc[i][7]);
    }
}

// ---------------- ba = hidden @ w_ba^T   ([L,64]) ---------------------------
__global__ __launch_bounds__(256) void ba_kernel(
    const float* __restrict__ hidden, const float* __restrict__ w_ba)
{
    __shared__ __align__(16) float hrow[HDIM];
    __shared__ float red[256];
    const int m = blockIdx.x;
    const int tid = threadIdx.x;
    for (int k = tid; k < HDIM; k += 256) hrow[k] = hidden[(size_t)m * HDIM + k];
    __syncthreads();
    const int n = tid & 63, part = tid >> 6;   // 64 outputs, 4-way split-K
    const float4* w4 = (const float4*)(w_ba + (size_t)n * HDIM + part * 512);
    const float4* h4 = (const float4*)(hrow + part * 512);
    float p = 0.f;
#pragma unroll 4
    for (int k = 0; k < 128; k++) {
        float4 a = h4[k], b = w4[k];
        p += a.x * b.x + a.y * b.y + a.z * b.z + a.w * b.w;
    }
    red[tid] = p;
    __syncthreads();
    if (tid < 64)
        g_ba[m * 64 + tid] = red[tid] + red[tid + 64] + red[tid + 128] + red[tid + 192];
}

// ---------------- causal depthwise conv (K=4) + SiLU ------------------------
__global__ __launch_bounds__(256) void conv_kernel(const float* __restrict__ conv_w)
{
    const int t = blockIdx.y;
    const int c = blockIdx.x * 256 + threadIdx.x;   // 0..8191
    int col;
    if (c < 2048)       col = (c >> 7) * 768 + (c & 127);            // q
    else if (c < 4096)  { int cc = c - 2048; col = (cc >> 7) * 768 + 128 + (cc & 127); }  // k
    else                { int cc = c - 4096; col = (cc >> 8) * 768 + 256 + (cc & 255); }  // v

    const float4 w = ((const float4*)conv_w)[c];
    float acc = 0.f;
    if (t >= 3) {
        size_t b = (size_t)(t - 3) * QKVZ_N + col;
        acc = g_qkvz[b] * w.x + g_qkvz[b + QKVZ_N] * w.y
            + g_qkvz[b + 2 * QKVZ_N] * w.z + g_qkvz[b + 3 * QKVZ_N] * w.w;
    } else {
        float ws[4] = {w.x, w.y, w.z, w.w};
#pragma unroll
        for (int j = 0; j < 4; j++) {
            int tt = t - 3 + j;
            if (tt >= 0) acc += g_qkvz[(size_t)tt * QKVZ_N + col] * ws[j];
        }
    }
    g_mixed[(size_t)t * MIXED_N + c] = acc / (1.f + expf(-acc));   // silu
}

// ---------------- q/k l2norm (+ q scale) ------------------------------------
__global__ __launch_bounds__(128) void prep_kernel()
{
    const int t = blockIdx.y, h = blockIdx.x, tid = threadIdx.x;
    __shared__ float s1[4], s2[4];
    const size_t base = (size_t)t * MIXED_N;
    float qv = g_mixed[base + h * DKD + tid];
    float kv = g_mixed[base + KEY_DIM + h * DKD + tid];
    float a = qv * qv, b = kv * kv;
#pragma unroll
    for (int o = 16; o > 0; o >>= 1) {
        a += __shfl_down_sync(0xffffffffu, a, o);
        b += __shfl_down_sync(0xffffffffu, b, o);
    }
    if ((tid & 31) == 0) { s1[tid >> 5] = a; s2[tid >> 5] = b; }
    __syncthreads();
    float qs = s1[0] + s1[1] + s1[2] + s1[3];
    float ks = s2[0] + s2[1] + s2[2] + s2[3];
    const size_t o = ((size_t)t * NKH + h) * DKD + tid;
    g_qn[o] = qv * rsqrtf(qs + 1e-6f) * 0.08838834764831845f;   // * DK^-0.5
    g_kn[o] = kv * rsqrtf(ks + 1e-6f);
}

// ---------------- gates: beta = sigmoid(b), g = -exp(a_log)*softplus(a+dt) --
__global__ __launch_bounds__(256) void gb_kernel(
    const float* __restrict__ dt_bias, const float* __restrict__ a_log)
{
    const int idx = blockIdx.x * 256 + threadIdx.x;   // < L*NV
    const int vh = idx & 31;
    const int t  = idx >> 5;
    const int h  = vh >> 1, i = vh & 1;
    float b = g_ba[t * 64 + h * 4 + i];
    float a = g_ba[t * 64 + h * 4 + 2 + i];
    g_bv[idx] = 1.f / (1.f + expf(-b));
    float x = a + dt_bias[vh];
    float sp = (x > 20.f) ? x : log1pf(expf(x));
    g_gv[idx] = -expf(a_log[vh]) * sp;
}

// ---------------- sequential delta-rule scan ---------------------------------
// grid (4 v-slices, 32 heads), 128 threads. thread (kq = tid>>5, v = tid&31)
// owns S[kq*32 .. kq*32+31][vslice*32 + v] in registers.
__global__ __launch_bounds__(128) void scan_kernel()
{
    const int head = blockIdx.y;     // value head 0..31
    const int vs   = blockIdx.x;     // v-slice 0..3
    const int tid  = threadIdx.x;
    const int v    = tid & 31;
    const int kq   = tid >> 5;
    const int kh   = head >> 1;      // key head

    __shared__ __align__(16) float ks[128];
    __shared__ __align__(16) float qs[128];
    __shared__ float vsm[32];
    __shared__ float red[4][32];
    __shared__ float red2[4][32];

    float s[32];
#pragma unroll
    for (int i = 0; i < 32; i++) s[i] = 0.f;
    float ksr[32];

    const int vcol = head * DVD + vs * 32;   // base column in [0,4096)

    for (int t = 0; t < LSEQ; t++) {
        const size_t kb = ((size_t)t * NKH + kh) * DKD;
        ks[tid] = g_kn[kb + tid];
        qs[tid] = g_qn[kb + tid];
        if (tid < 32) vsm[tid] = g_mixed[(size_t)t * MIXED_N + KEY_DIM * 2 + vcol + tid];
        const float gt = g_gv[t * NVH + head];
        const float bt = g_bv[t * NVH + head];
        __syncthreads();                                 // A: inputs visible

        // partial kv = sum over this thread's 32 k-rows
        const float4* k4 = (const float4*)(ks + kq * 32);
        float p = 0.f;
#pragma unroll
        for (int i = 0; i < 8; i++) {
            float4 kk = k4[i];
            ksr[4*i+0] = kk.x; ksr[4*i+1] = kk.y; ksr[4*i+2] = kk.z; ksr[4*i+3] = kk.w;
            p += s[4*i+0]*kk.x + s[4*i+1]*kk.y + s[4*i+2]*kk.z + s[4*i+3]*kk.w;
        }
        red[kq][v] = p;
        __syncthreads();                                 // B: partials ready

        const float eg = expf(gt);
        const float kvsum = red[0][v] + red[1][v] + red[2][v] + red[3][v];
        const float delta = (vsm[v] - eg * kvsum) * bt;

        const float4* q4 = (const float4*)(qs + kq * 32);
        float op = 0.f;
#pragma unroll
        for (int i = 0; i < 8; i++) {
            float4 qq = q4[i];
            float s0 = eg * s[4*i+0] + ksr[4*i+0] * delta; s[4*i+0] = s0; op += s0 * qq.x;
            float s1 = eg * s[4*i+1] + ksr[4*i+1] * delta; s[4*i+1] = s1; op += s1 * qq.y;
            float s2 = eg * s[4*i+2] + ksr[4*i+2] * delta; s[4*i+2] = s2; op += s2 * qq.z;
            float s3 = eg * s[4*i+3] + ksr[4*i+3] * delta; s[4*i+3] = s3; op += s3 * qq.w;
        }
        red2[kq][v] = op;
        __syncthreads();                                 // C: o partials ready

        if (kq == 0) {
            float o = red2[0][v] + red2[1][v] + red2[2][v] + red2[3][v];
            g_core[(size_t)t * VAL_DIM + vcol + v] = o;
        }
    }
}

// ---------------- RMSNorm over DV + norm_w + silu(z) gate -------------------
__global__ __launch_bounds__(128) void gate_kernel(const float* __restrict__ norm_w)
{
    const int t = blockIdx.y, vh = blockIdx.x, tid = threadIdx.x;
    __shared__ float sm[4];
    const size_t ci = (size_t)t * VAL_DIM + vh * DVD + tid;
    float c = g_core[ci];
    float ss = c * c;
#pragma unroll
    for (int o = 16; o > 0; o >>= 1) ss += __shfl_down_sync(0xffffffffu, ss, o);
    if ((tid & 31) == 0) sm[tid >> 5] = ss;
    __syncthreads();
    float sum = sm[0] + sm[1] + sm[2] + sm[3];
    float r = rsqrtf(sum * (1.0f / 128.0f) + 1e-6f);
    float z = g_qkvz[(size_t)t * QKVZ_N + (vh >> 1) * 768 + 512 + (vh & 1) * 128 + tid];
    float sz = z / (1.f + expf(-z));
    g_gated[ci] = c * r * norm_w[tid] * sz;
}

// ---------------- launch ------------------------------------------------------
extern "C" void kernel_launch(void* const* d_in, const int* in_sizes, int n_in,
                              void* d_out, int out_size)
{
    const float* hidden  = (const float*)d_in[0];
    const float* w_qkvz  = (const float*)d_in[1];
    const float* w_ba    = (const float*)d_in[2];
    const float* conv_w  = (const float*)d_in[3];
    const float* dt_bias = (const float*)d_in[4];
    const float* a_log   = (const float*)d_in[5];
    const float* norm_w  = (const float*)d_in[6];
    const float* w_out   = (const float*)d_in[7];
    float* out = (float*)d_out;

    float *p_qkvz = nullptr, *p_gated = nullptr;
    cudaGetSymbolAddress((void**)&p_qkvz,  g_qkvz);
    cudaGetSymbolAddress((void**)&p_gated, g_gated);

    // 1) qkvz = hidden @ w_qkvz^T   [4096, 12288]
    sgemm_nt<<<dim3(QKVZ_N / 128, LSEQ / 128), 256>>>(hidden, w_qkvz, p_qkvz, LSEQ, QKVZ_N, HDIM);
    // 2) ba = hidden @ w_ba^T       [4096, 64]
    ba_kernel<<<LSEQ, 256>>>(hidden, w_ba);
    // 3) causal conv + silu -> mixed [4096, 8192]
    conv_kernel<<<dim3(MIXED_N / 256, LSEQ), 256>>>(conv_w);
    // 4) l2norm q,k
    prep_kernel<<<dim3(NKH, LSEQ), 128>>>();
    // 5) gates
    gb_kernel<<<(LSEQ * NVH) / 256, 256>>>(dt_bias, a_log);
    // 6) delta-rule scan
    scan_kernel<<<dim3(4, NVH), 128>>>();
    // 7) rmsnorm + gate
    gate_kernel<<<dim3(NVH, LSEQ), 128>>>(norm_w);
    // 8) out = gated @ w_out^T     [4096, 2048]
    sgemm_nt<<<dim3(HDIM / 128, LSEQ / 128), 256>>>(p_gated, w_out, out, LSEQ, HDIM, VAL_DIM);
}

// round 3
// speedup vs baseline: 1.6031x; 1.6031x over previous
#include <cuda_runtime.h>
#include <cuda_bf16.h>
#include <math.h>
#include <stdint.h>

// ---------------- problem constants ----------------
#define LSEQ   4096
#define HDIM   2048
#define NKH    16
#define NVH    32
#define DKD    128
#define DVD    128
#define QKVZ_N 12288            // 2*KEY_DIM + 2*VAL_DIM
#define MIXED_N 8192            // 2*KEY_DIM + VAL_DIM
#define KEY_DIM 2048
#define VAL_DIM 4096

// K' = 3*K for the 3-term bf16 split GEMMs
#define KP1 (3 * HDIM)      // 6144
#define KP2 (3 * VAL_DIM)   // 12288

// ---------------- scratch (static device memory; no allocs allowed) --------
__device__ float g_qkvz [LSEQ * QKVZ_N];
__device__ float g_ba   [LSEQ * 64];
__device__ float g_mixed[LSEQ * MIXED_N];
__device__ float g_qn   [LSEQ * NKH * DKD];
__device__ float g_kn   [LSEQ * NKH * DKD];
__device__ float g_gv   [LSEQ * NVH];
__device__ float g_bv   [LSEQ * NVH];
__device__ float g_core [LSEQ * NVH * DVD];

__device__ __nv_bfloat16 g_a1[(size_t)LSEQ * KP1];      // hidden  split [hi,lo,hi]
__device__ __nv_bfloat16 g_b1[(size_t)QKVZ_N * KP1];    // w_qkvz  split [hi,hi,lo]
__device__ __nv_bfloat16 g_a2[(size_t)LSEQ * KP2];      // gated   split [hi,lo,hi]
__device__ __nv_bfloat16 g_b2[(size_t)HDIM * KP2];      // w_out   split [hi,hi,lo]

// =================== low-level helpers ===============
__device__ __forceinline__ uint32_t smem_to_u32(const void* p) {
    uint32_t a;
    asm("{ .reg .u64 t; cvta.to.shared.u64 t, %1; cvt.u32.u64 %0, t; }" : "=r"(a) : "l"(p));
    return a;
}
__device__ __forceinline__ void cp_async16(uint32_t saddr, const void* gptr) {
    asm volatile("cp.async.cg.shared.global [%0], [%1], 16;" :: "r"(saddr), "l"(gptr));
}
#define CP_COMMIT() asm volatile("cp.async.commit_group;" ::: "memory")
#define CP_WAIT1()  asm volatile("cp.async.wait_group 1;"  ::: "memory")

__device__ __forceinline__ void ldmatrix_x4(
    uint32_t& r0, uint32_t& r1, uint32_t& r2, uint32_t& r3, uint32_t addr)
{
    asm volatile("ldmatrix.sync.aligned.m8n8.x4.shared.b16 {%0,%1,%2,%3}, [%4];"
        : "=r"(r0), "=r"(r1), "=r"(r2), "=r"(r3) : "r"(addr));
}
__device__ __forceinline__ void mma16816(
    float* c, uint32_t a0, uint32_t a1, uint32_t a2, uint32_t a3,
    uint32_t b0, uint32_t b1)
{
    asm volatile(
        "mma.sync.aligned.m16n8k16.row.col.f32.bf16.bf16.f32 "
        "{%0,%1,%2,%3}, {%4,%5,%6,%7}, {%8,%9}, {%0,%1,%2,%3};"
        : "+f"(c[0]), "+f"(c[1]), "+f"(c[2]), "+f"(c[3])
        : "r"(a0), "r"(a1), "r"(a2), "r"(a3), "r"(b0), "r"(b1));
}

// =================== bf16 mma.sync GEMM: C[M,N] = A[M,Kp] * B[N,Kp]^T =======
// BM=128, BN=128, BK=32. 256 threads (8 warps, 4x2), warp tile 32x64.
// SMEM rows padded to 40 elems (80B) -> conflict-free ldmatrix.
#define GBK     32
#define GSTRIDE 40
#define GOP_ELE (128 * GSTRIDE)

__global__ __launch_bounds__(256, 2) void mma_gemm(
    const __nv_bfloat16* __restrict__ A, const __nv_bfloat16* __restrict__ B,
    float* __restrict__ C, int N, int Kp)
{
    __shared__ __align__(16) __nv_bfloat16 sA[2][GOP_ELE];
    __shared__ __align__(16) __nv_bfloat16 sB[2][GOP_ELE];

    const int tid  = threadIdx.x;
    const int wid  = tid >> 5, lane = tid & 31;
    const int bn   = blockIdx.x, bm = blockIdx.y;
    const int NT   = Kp / GBK;

    const uint32_t sA0 = smem_to_u32(&sA[0][0]);
    const uint32_t sB0 = smem_to_u32(&sB[0][0]);
    const uint32_t stageA = (uint32_t)(GOP_ELE * 2);   // bytes between stages
    const uint32_t stageB = (uint32_t)(GOP_ELE * 2);

    // global bases
    const __nv_bfloat16* Ag = A + (size_t)(bm * 128) * Kp;
    const __nv_bfloat16* Bg = B + (size_t)(bn * 128) * Kp;

    // per-thread load mapping: 512 chunks of 16B per operand, 2 per thread
    const int l_row0 = (tid)       >> 2, l_c0 = (tid)       & 3;
    const int l_row1 = (tid + 256) >> 2, l_c1 = (tid + 256) & 3;

    // warp tile: warp_m = wid&3 (32 rows), warp_n = wid>>2 (64 cols)
    const int wr = (wid & 3) * 32;
    const int wc = (wid >> 2) * 64;

    // ldmatrix lane addressing (element offsets; *2 for bytes)
    const int a_row    = wr + (lane & 15);
    const int a_colsel = (lane >> 4) << 3;            // 0 or 8
    const int b_row    = wc + ((lane >> 4) << 3) + (lane & 7);
    const int b_colsel = ((lane >> 3) & 1) << 3;      // 0 or 8

    float acc[2][8][4];
#pragma unroll
    for (int i = 0; i < 2; i++)
#pragma unroll
        for (int j = 0; j < 8; j++)
#pragma unroll
            for (int k = 0; k < 4; k++) acc[i][j][k] = 0.f;

    // prologue: stages 0,1
#pragma unroll
    for (int s = 0; s < 2; s++) {
        const __nv_bfloat16* Ak = Ag + s * GBK;
        const __nv_bfloat16* Bk = Bg + s * GBK;
        cp_async16(sA0 + s * stageA + (l_row0 * GSTRIDE + l_c0 * 8) * 2, Ak + (size_t)l_row0 * Kp + l_c0 * 8);
        cp_async16(sA0 + s * stageA + (l_row1 * GSTRIDE + l_c1 * 8) * 2, Ak + (size_t)l_row1 * Kp + l_c1 * 8);
        cp_async16(sB0 + s * stageB + (l_row0 * GSTRIDE + l_c0 * 8) * 2, Bk + (size_t)l_row0 * Kp + l_c0 * 8);
        cp_async16(sB0 + s * stageB + (l_row1 * GSTRIDE + l_c1 * 8) * 2, Bk + (size_t)l_row1 * Kp + l_c1 * 8);
        CP_COMMIT();
    }

    for (int kt = 0; kt < NT; kt++) {
        const int s = kt & 1;
        CP_WAIT1();
        __syncthreads();

        const uint32_t aS = sA0 + s * stageA;
        const uint32_t bS = sB0 + s * stageB;
#pragma unroll
        for (int kk = 0; kk < GBK; kk += 16) {
            uint32_t af[2][4];
#pragma unroll
            for (int mi = 0; mi < 2; mi++) {
                uint32_t addr = aS + ((a_row + mi * 16) * GSTRIDE + kk + a_colsel) * 2;
                ldmatrix_x4(af[mi][0], af[mi][1], af[mi][2], af[mi][3], addr);
            }
            uint32_t bf[8][2];
#pragma unroll
            for (int p = 0; p < 4; p++) {
                uint32_t addr = bS + ((b_row + p * 16) * GSTRIDE + kk + b_colsel) * 2;
                uint32_t r0, r1, r2, r3;
                ldmatrix_x4(r0, r1, r2, r3, addr);
                bf[2 * p][0] = r0; bf[2 * p][1] = r1;
                bf[2 * p + 1][0] = r2; bf[2 * p + 1][1] = r3;
            }
#pragma unroll
            for (int mi = 0; mi < 2; mi++)
#pragma unroll
                for (int nj = 0; nj < 8; nj++)
                    mma16816(acc[mi][nj], af[mi][0], af[mi][1], af[mi][2], af[mi][3],
                             bf[nj][0], bf[nj][1]);
        }
        __syncthreads();

        if (kt + 2 < NT) {
            const __nv_bfloat16* Ak = Ag + (kt + 2) * GBK;
            const __nv_bfloat16* Bk = Bg + (kt + 2) * GBK;
            cp_async16(sA0 + s * stageA + (l_row0 * GSTRIDE + l_c0 * 8) * 2, Ak + (size_t)l_row0 * Kp + l_c0 * 8);
            cp_async16(sA0 + s * stageA + (l_row1 * GSTRIDE + l_c1 * 8) * 2, Ak + (size_t)l_row1 * Kp + l_c1 * 8);
            cp_async16(sB0 + s * stageB + (l_row0 * GSTRIDE + l_c0 * 8) * 2, Bk + (size_t)l_row0 * Kp + l_c0 * 8);
            cp_async16(sB0 + s * stageB + (l_row1 * GSTRIDE + l_c1 * 8) * 2, Bk + (size_t)l_row1 * Kp + l_c1 * 8);
        }
        CP_COMMIT();   // keep group count in lockstep even on tail iterations
    }

    // epilogue: write fp32 accumulators
    const int g = lane >> 2, t = lane & 3;
    const size_t row_base = (size_t)(bm * 128 + wr);
    const int    col_base = bn * 128 + wc;
#pragma unroll
    for (int mi = 0; mi < 2; mi++) {
#pragma unroll
        for (int nj = 0; nj < 8; nj++) {
            size_t r0 = row_base + mi * 16 + g;
            int    c  = col_base + nj * 8 + t * 2;
            *(float2*)(C + r0 * N + c)       = make_float2(acc[mi][nj][0], acc[mi][nj][1]);
            *(float2*)(C + (r0 + 8) * N + c) = make_float2(acc[mi][nj][2], acc[mi][nj][3]);
        }
    }
}

// =================== bf16 hi/lo split conversions ===========================
// mode 0 (A-operand): [hi, lo, hi]   mode 1 (B-operand): [hi, hi, lo]
__global__ __launch_bounds__(256) void cvt_split(
    const float* __restrict__ src, __nv_bfloat16* __restrict__ dst,
    int C, int total4, int mode)
{
    int i4 = blockIdx.x * 256 + threadIdx.x;
    if (i4 >= total4) return;
    int per_row = C >> 2;
    int r = i4 / per_row, c4 = i4 - r * per_row;
    float4 v = ((const float4*)src)[i4];
    float x[4] = {v.x, v.y, v.z, v.w};
    __nv_bfloat16 h[4], l[4];
#pragma unroll
    for (int i = 0; i < 4; i++) {
        h[i] = __float2bfloat16(x[i]);
        l[i] = __float2bfloat16(x[i] - __bfloat162float(h[i]));
    }
    uint32_t hp0, hp1, lp0, lp1;
    {
        __nv_bfloat162 a = __halves2bfloat162(h[0], h[1]);
        __nv_bfloat162 b = __halves2bfloat162(h[2], h[3]);
        hp0 = *(uint32_t*)&a; hp1 = *(uint32_t*)&b;
        __nv_bfloat162 c = __halves2bfloat162(l[0], l[1]);
        __nv_bfloat162 d = __halves2bfloat162(l[2], l[3]);
        lp0 = *(uint32_t*)&c; lp1 = *(uint32_t*)&d;
    }
    size_t base = (size_t)r * (3 * C) + c4 * 4;
    uint2* d0 = (uint2*)(dst + base);
    uint2* d1 = (uint2*)(dst + base + C);
    uint2* d2 = (uint2*)(dst + base + 2 * C);
    *d0 = make_uint2(hp0, hp1);
    if (mode == 0) { *d1 = make_uint2(lp0, lp1); *d2 = make_uint2(hp0, hp1); }
    else           { *d1 = make_uint2(hp0, hp1); *d2 = make_uint2(lp0, lp1); }
}

// ---------------- ba = hidden @ w_ba^T   ([L,64]) ---------------------------
__global__ __launch_bounds__(256) void ba_kernel(
    const float* __restrict__ hidden, const float* __restrict__ w_ba)
{
    __shared__ __align__(16) float hrow[HDIM];
    __shared__ float red[256];
    const int m = blockIdx.x;
    const int tid = threadIdx.x;
    for (int k = tid; k < HDIM; k += 256) hrow[k] = hidden[(size_t)m * HDIM + k];
    __syncthreads();
    const int n = tid & 63, part = tid >> 6;
    const float4* w4 = (const float4*)(w_ba + (size_t)n * HDIM + part * 512);
    const float4* h4 = (const float4*)(hrow + part * 512);
    float p = 0.f;
#pragma unroll 4
    for (int k = 0; k < 128; k++) {
        float4 a = h4[k], b = w4[k];
        p += a.x * b.x + a.y * b.y + a.z * b.z + a.w * b.w;
    }
    red[tid] = p;
    __syncthreads();
    if (tid < 64)
        g_ba[m * 64 + tid] = red[tid] + red[tid + 64] + red[tid + 128] + red[tid + 192];
}

// ---------------- causal depthwise conv (K=4) + SiLU ------------------------
__global__ __launch_bounds__(256) void conv_kernel(const float* __restrict__ conv_w)
{
    const int t = blockIdx.y;
    const int c = blockIdx.x * 256 + threadIdx.x;
    int col;
    if (c < 2048)       col = (c >> 7) * 768 + (c & 127);
    else if (c < 4096)  { int cc = c - 2048; col = (cc >> 7) * 768 + 128 + (cc & 127); }
    else                { int cc = c - 4096; col = (cc >> 8) * 768 + 256 + (cc & 255); }

    const float4 w = ((const float4*)conv_w)[c];
    float acc = 0.f;
    if (t >= 3) {
        size_t b = (size_t)(t - 3) * QKVZ_N + col;
        acc = g_qkvz[b] * w.x + g_qkvz[b + QKVZ_N] * w.y
            + g_qkvz[b + 2 * QKVZ_N] * w.z + g_qkvz[b + 3 * QKVZ_N] * w.w;
    } else {
        float ws[4] = {w.x, w.y, w.z, w.w};
#pragma unroll
        for (int j = 0; j < 4; j++) {
            int tt = t - 3 + j;
            if (tt >= 0) acc += g_qkvz[(size_t)tt * QKVZ_N + col] * ws[j];
        }
    }
    g_mixed[(size_t)t * MIXED_N + c] = acc / (1.f + expf(-acc));
}

// ---------------- q/k l2norm (+ q scale) ------------------------------------
__global__ __launch_bounds__(128) void prep_kernel()
{
    const int t = blockIdx.y, h = blockIdx.x, tid = threadIdx.x;
    __shared__ float s1[4], s2[4];
    const size_t base = (size_t)t * MIXED_N;
    float qv = g_mixed[base + h * DKD + tid];
    float kv = g_mixed[base + KEY_DIM + h * DKD + tid];
    float a = qv * qv, b = kv * kv;
#pragma unroll
    for (int o = 16; o > 0; o >>= 1) {
        a += __shfl_down_sync(0xffffffffu, a, o);
        b += __shfl_down_sync(0xffffffffu, b, o);
    }
    if ((tid & 31) == 0) { s1[tid >> 5] = a; s2[tid >> 5] = b; }
    __syncthreads();
    float qs = s1[0] + s1[1] + s1[2] + s1[3];
    float ks = s2[0] + s2[1] + s2[2] + s2[3];
    const size_t o = ((size_t)t * NKH + h) * DKD + tid;
    g_qn[o] = qv * rsqrtf(qs + 1e-6f) * 0.08838834764831845f;
    g_kn[o] = kv * rsqrtf(ks + 1e-6f);
}

// ---------------- gates ------------------------------------------------------
__global__ __launch_bounds__(256) void gb_kernel(
    const float* __restrict__ dt_bias, const float* __restrict__ a_log)
{
    const int idx = blockIdx.x * 256 + threadIdx.x;
    const int vh = idx & 31;
    const int t  = idx >> 5;
    const int h  = vh >> 1, i = vh & 1;
    float b = g_ba[t * 64 + h * 4 + i];
    float a = g_ba[t * 64 + h * 4 + 2 + i];
    g_bv[idx] = 1.f / (1.f + expf(-b));
    float x = a + dt_bias[vh];
    float sp = (x > 20.f) ? x : log1pf(expf(x));
    g_gv[idx] = -expf(a_log[vh]) * sp;
}

// ---------------- sequential delta-rule scan ---------------------------------
__global__ __launch_bounds__(128) void scan_kernel()
{
    const int head = blockIdx.y;
    const int vs   = blockIdx.x;
    const int tid  = threadIdx.x;
    const int v    = tid & 31;
    const int kq   = tid >> 5;
    const int kh   = head >> 1;

    __shared__ __align__(16) float ks[128];
    __shared__ __align__(16) float qs[128];
    __shared__ float vsm[32];
    __shared__ float red[4][32];
    __shared__ float red2[4][32];

    float s[32];
#pragma unroll
    for (int i = 0; i < 32; i++) s[i] = 0.f;
    float ksr[32];

    const int vcol = head * DVD + vs * 32;

    for (int t = 0; t < LSEQ; t++) {
        const size_t kb = ((size_t)t * NKH + kh) * DKD;
        ks[tid] = g_kn[kb + tid];
        qs[tid] = g_qn[kb + tid];
        if (tid < 32) vsm[tid] = g_mixed[(size_t)t * MIXED_N + KEY_DIM * 2 + vcol + tid];
        const float gt = g_gv[t * NVH + head];
        const float bt = g_bv[t * NVH + head];
        __syncthreads();

        const float4* k4 = (const float4*)(ks + kq * 32);
        float p = 0.f;
#pragma unroll
        for (int i = 0; i < 8; i++) {
            float4 kk = k4[i];
            ksr[4*i+0] = kk.x; ksr[4*i+1] = kk.y; ksr[4*i+2] = kk.z; ksr[4*i+3] = kk.w;
            p += s[4*i+0]*kk.x + s[4*i+1]*kk.y + s[4*i+2]*kk.z + s[4*i+3]*kk.w;
        }
        red[kq][v] = p;
        __syncthreads();

        const float eg = expf(gt);
        const float kvsum = red[0][v] + red[1][v] + red[2][v] + red[3][v];
        const float delta = (vsm[v] - eg * kvsum) * bt;

        const float4* q4 = (const float4*)(qs + kq * 32);
        float op = 0.f;
#pragma unroll
        for (int i = 0; i < 8; i++) {
            float4 qq = q4[i];
            float s0 = eg * s[4*i+0] + ksr[4*i+0] * delta; s[4*i+0] = s0; op += s0 * qq.x;
            float s1 = eg * s[4*i+1] + ksr[4*i+1] * delta; s[4*i+1] = s1; op += s1 * qq.y;
            float s2 = eg * s[4*i+2] + ksr[4*i+2] * delta; s[4*i+2] = s2; op += s2 * qq.z;
            float s3 = eg * s[4*i+3] + ksr[4*i+3] * delta; s[4*i+3] = s3; op += s3 * qq.w;
        }
        red2[kq][v] = op;
        __syncthreads();

        if (kq == 0) {
            float o = red2[0][v] + red2[1][v] + red2[2][v] + red2[3][v];
            g_core[(size_t)t * VAL_DIM + vcol + v] = o;
        }
    }
}

// ---------------- RMSNorm + gate; writes bf16 [hi,lo,hi] for GEMM2 ----------
__global__ __launch_bounds__(128) void gate_kernel(const float* __restrict__ norm_w)
{
    const int t = blockIdx.y, vh = blockIdx.x, tid = threadIdx.x;
    __shared__ float sm[4];
    const size_t ci = (size_t)t * VAL_DIM + vh * DVD + tid;
    float c = g_core[ci];
    float ss = c * c;
#pragma unroll
    for (int o = 16; o > 0; o >>= 1) ss += __shfl_down_sync(0xffffffffu, ss, o);
    if ((tid & 31) == 0) sm[tid >> 5] = ss;
    __syncthreads();
    float sum = sm[0] + sm[1] + sm[2] + sm[3];
    float r = rsqrtf(sum * (1.0f / 128.0f) + 1e-6f);
    float z = g_qkvz[(size_t)t * QKVZ_N + (vh >> 1) * 768 + 512 + (vh & 1) * 128 + tid];
    float sz = z / (1.f + expf(-z));
    float x = c * r * norm_w[tid] * sz;

    __nv_bfloat16 hi = __float2bfloat16(x);
    __nv_bfloat16 lo = __float2bfloat16(x - __bfloat162float(hi));
    const size_t rb = (size_t)t * KP2;
    const int col = vh * DVD + tid;
    g_a2[rb + col]                = hi;
    g_a2[rb + VAL_DIM + col]      = lo;
    g_a2[rb + 2 * VAL_DIM + col]  = hi;
}

// ---------------- launch ------------------------------------------------------
extern "C" void kernel_launch(void* const* d_in, const int* in_sizes, int n_in,
                              void* d_out, int out_size)
{
    const float* hidden  = (const float*)d_in[0];
    const float* w_qkvz  = (const float*)d_in[1];
    const float* w_ba    = (const float*)d_in[2];
    const float* conv_w  = (const float*)d_in[3];
    const float* dt_bias = (const float*)d_in[4];
    const float* a_log   = (const float*)d_in[5];
    const float* norm_w  = (const float*)d_in[6];
    const float* w_out   = (const float*)d_in[7];
    float* out = (float*)d_out;

    float *p_qkvz = nullptr;
    __nv_bfloat16 *p_a1, *p_b1, *p_a2, *p_b2;
    cudaGetSymbolAddress((void**)&p_qkvz, g_qkvz);
    cudaGetSymbolAddress((void**)&p_a1, g_a1);
    cudaGetSymbolAddress((void**)&p_b1, g_b1);
    cudaGetSymbolAddress((void**)&p_a2, g_a2);
    cudaGetSymbolAddress((void**)&p_b2, g_b2);

    // split conversions for GEMM1 operands + GEMM2 B operand
    { int t4 = (LSEQ * HDIM) / 4;    cvt_split<<<(t4 + 255) / 256, 256>>>(hidden, p_a1, HDIM, t4, 0); }
    { int t4 = (QKVZ_N * HDIM) / 4;  cvt_split<<<(t4 + 255) / 256, 256>>>(w_qkvz, p_b1, HDIM, t4, 1); }
    { int t4 = (HDIM * VAL_DIM) / 4; cvt_split<<<(t4 + 255) / 256, 256>>>(w_out,  p_b2, VAL_DIM, t4, 1); }

    // 1) qkvz = hidden @ w_qkvz^T  (bf16 mma.sync, 3-term split)
    mma_gemm<<<dim3(QKVZ_N / 128, LSEQ / 128), 256>>>(p_a1, p_b1, p_qkvz, QKVZ_N, KP1);
    // 2) ba
    ba_kernel<<<LSEQ, 256>>>(hidden, w_ba);
    // 3) conv + silu
    conv_kernel<<<dim3(MIXED_N / 256, LSEQ), 256>>>(conv_w);
    // 4) l2norm q,k
    prep_kernel<<<dim3(NKH, LSEQ), 128>>>();
    // 5) gates
    gb_kernel<<<(LSEQ * NVH) / 256, 256>>>(dt_bias, a_log);
    // 6) scan
    scan_kernel<<<dim3(4, NVH), 128>>>();
    // 7) rmsnorm + gate (emits bf16 split operand)
    gate_kernel<<<dim3(NVH, LSEQ), 128>>>(norm_w);
    // 8) out = gated @ w_out^T (bf16 mma.sync)
    mma_gemm<<<dim3(HDIM / 128, LSEQ / 128), 256>>>(p_a2, p_b2, out, HDIM, KP2);
}

// round 4
// speedup vs baseline: 1.8810x; 1.1734x over previous
#include <cuda_runtime.h>
#include <cuda_bf16.h>
#include <math.h>
#include <stdint.h>

// ---------------- problem constants ----------------
#define LSEQ   4096
#define HDIM   2048
#define NKH    16
#define NVH    32
#define DKD    128
#define DVD    128
#define QKVZ_N 12288            // 2*KEY_DIM + 2*VAL_DIM
#define MIXED_N 8192            // 2*KEY_DIM + VAL_DIM
#define KEY_DIM 2048
#define VAL_DIM 4096

// K' = 3*K for the 3-term bf16 split GEMMs
#define KP1 (3 * HDIM)      // 6144
#define KP2 (3 * VAL_DIM)   // 12288

// ---------------- scratch (static device memory; no allocs allowed) --------
__device__ float g_qkvz [LSEQ * QKVZ_N];
__device__ float g_ba   [LSEQ * 64];
__device__ float g_mixed[LSEQ * MIXED_N];
__device__ float g_qn   [LSEQ * NKH * DKD];
__device__ float g_kn   [LSEQ * NKH * DKD];
__device__ float g_gv   [LSEQ * NVH];
__device__ float g_bv   [LSEQ * NVH];
__device__ float g_core [LSEQ * NVH * DVD];

__device__ __nv_bfloat16 g_a1[(size_t)LSEQ * KP1];      // hidden  split [hi,lo,hi]
__device__ __nv_bfloat16 g_b1[(size_t)QKVZ_N * KP1];    // w_qkvz  split [hi,hi,lo]
__device__ __nv_bfloat16 g_a2[(size_t)LSEQ * KP2];      // gated   split [hi,lo,hi]
__device__ __nv_bfloat16 g_b2[(size_t)HDIM * KP2];      // w_out   split [hi,hi,lo]

// =================== low-level helpers ===============
__device__ __forceinline__ uint32_t smem_to_u32(const void* p) {
    uint32_t a;
    asm("{ .reg .u64 t; cvta.to.shared.u64 t, %1; cvt.u32.u64 %0, t; }" : "=r"(a) : "l"(p));
    return a;
}
__device__ __forceinline__ void cp_async16(uint32_t saddr, const void* gptr) {
    asm volatile("cp.async.cg.shared.global [%0], [%1], 16;" :: "r"(saddr), "l"(gptr));
}
#define CP_COMMIT() asm volatile("cp.async.commit_group;" ::: "memory")
#define CP_WAIT2()  asm volatile("cp.async.wait_group 2;"  ::: "memory")

__device__ __forceinline__ void ldmatrix_x4(
    uint32_t& r0, uint32_t& r1, uint32_t& r2, uint32_t& r3, uint32_t addr)
{
    asm volatile("ldmatrix.sync.aligned.m8n8.x4.shared.b16 {%0,%1,%2,%3}, [%4];"
        : "=r"(r0), "=r"(r1), "=r"(r2), "=r"(r3) : "r"(addr));
}
__device__ __forceinline__ void mma16816(
    float* c, uint32_t a0, uint32_t a1, uint32_t a2, uint32_t a3,
    uint32_t b0, uint32_t b1)
{
    asm volatile(
        "mma.sync.aligned.m16n8k16.row.col.f32.bf16.bf16.f32 "
        "{%0,%1,%2,%3}, {%4,%5,%6,%7}, {%8,%9}, {%0,%1,%2,%3};"
        : "+f"(c[0]), "+f"(c[1]), "+f"(c[2]), "+f"(c[3])
        : "r"(a0), "r"(a1), "r"(a2), "r"(a3), "r"(b0), "r"(b1));
}

// =================== bf16 mma.sync GEMM: C[M,N] = A[M,Kp] * B[N,Kp]^T =======
// BM=128, BN=256, BK=32. 256 threads (8 warps 2Mx4N), warp tile 64x64.
// 4-stage cp.async ring; SMEM rows padded to 40 elems -> conflict-free ldmatrix.
#define GBK     32
#define GSTRIDE 40
#define NSTG    4
#define A_STG_ELE (128 * GSTRIDE)     // 5120 bf16
#define B_STG_ELE (256 * GSTRIDE)     // 10240 bf16
#define GEMM_SMEM ((A_STG_ELE + B_STG_ELE) * NSTG * 2)   // 122880 bytes

__global__ void __launch_bounds__(256, 1) mma_gemm(
    const __nv_bfloat16* __restrict__ A, const __nv_bfloat16* __restrict__ B,
    float* __restrict__ C, int N, int Kp)
{
    extern __shared__ __align__(16) __nv_bfloat16 smem[];
    const uint32_t sAu = smem_to_u32(smem);
    const uint32_t sBu = sAu + NSTG * A_STG_ELE * 2;

    const int tid  = threadIdx.x;
    const int wid  = tid >> 5, lane = tid & 31;
    const int NT   = Kp / GBK;

    // L2-friendly rasterization: 8-row bm bands
    const int bnT = gridDim.x;
    const int id   = blockIdx.y * bnT + blockIdx.x;
    const int band = id / (8 * bnT);
    const int rem  = id % (8 * bnT);
    const int bm   = band * 8 + (rem & 7);
    const int bn   = rem >> 3;

    const __nv_bfloat16* Ag = A + (size_t)(bm * 128) * Kp;
    const __nv_bfloat16* Bg = B + (size_t)(bn * 256) * Kp;

    // warp tile: 2 warps over M (64 each), 4 warps over N (64 each)
    const int wr = (wid & 1) * 64;
    const int wc = (wid >> 1) * 64;

    // ldmatrix lane addressing (element offsets)
    const int a_row    = wr + (lane & 15);
    const int a_colsel = (lane >> 4) << 3;
    const int b_row    = wc + ((lane >> 4) << 3) + (lane & 7);
    const int b_colsel = ((lane >> 3) & 1) << 3;

    float acc[4][8][4];
#pragma unroll
    for (int i = 0; i < 4; i++)
#pragma unroll
        for (int j = 0; j < 8; j++)
#pragma unroll
            for (int k = 0; k < 4; k++) acc[i][j][k] = 0.f;

    // per-stage load: A 512 chunks (2/thread), B 1024 chunks (4/thread)
    #define LOAD_STAGE(kt_, s_) do { \
        const __nv_bfloat16* Ak_ = Ag + (kt_) * GBK; \
        const __nv_bfloat16* Bk_ = Bg + (kt_) * GBK; \
        const uint32_t aS_ = sAu + (s_) * (A_STG_ELE * 2); \
        const uint32_t bS_ = sBu + (s_) * (B_STG_ELE * 2); \
        _Pragma("unroll") \
        for (int j_ = 0; j_ < 2; j_++) { \
            int c_ = tid + j_ * 256; int row_ = c_ >> 2, cc_ = c_ & 3; \
            cp_async16(aS_ + (row_ * GSTRIDE + cc_ * 8) * 2, Ak_ + (size_t)row_ * Kp + cc_ * 8); \
        } \
        _Pragma("unroll") \
        for (int j_ = 0; j_ < 4; j_++) { \
            int c_ = tid + j_ * 256; int row_ = c_ >> 2, cc_ = c_ & 3; \
            cp_async16(bS_ + (row_ * GSTRIDE + cc_ * 8) * 2, Bk_ + (size_t)row_ * Kp + cc_ * 8); \
        } \
        CP_COMMIT(); \
    } while (0)

    LOAD_STAGE(0, 0);
    LOAD_STAGE(1, 1);
    LOAD_STAGE(2, 2);

    for (int kt = 0; kt < NT; kt++) {
        const int s = kt & 3;
        CP_WAIT2();
        __syncthreads();

        const uint32_t aS = sAu + s * (A_STG_ELE * 2);
        const uint32_t bS = sBu + s * (B_STG_ELE * 2);
#pragma unroll
        for (int kk = 0; kk < GBK; kk += 16) {
            uint32_t af[4][4];
#pragma unroll
            for (int mi = 0; mi < 4; mi++) {
                uint32_t addr = aS + ((a_row + mi * 16) * GSTRIDE + kk + a_colsel) * 2;
                ldmatrix_x4(af[mi][0], af[mi][1], af[mi][2], af[mi][3], addr);
            }
            uint32_t bf[8][2];
#pragma unroll
            for (int p = 0; p < 4; p++) {
                uint32_t addr = bS + ((b_row + p * 16) * GSTRIDE + kk + b_colsel) * 2;
                uint32_t r0, r1, r2, r3;
                ldmatrix_x4(r0, r1, r2, r3, addr);
                bf[2 * p][0] = r0; bf[2 * p][1] = r1;
                bf[2 * p + 1][0] = r2; bf[2 * p + 1][1] = r3;
            }
#pragma unroll
            for (int mi = 0; mi < 4; mi++)
#pragma unroll
                for (int nj = 0; nj < 8; nj++)
                    mma16816(acc[mi][nj], af[mi][0], af[mi][1], af[mi][2], af[mi][3],
                             bf[nj][0], bf[nj][1]);
        }

        if (kt + 3 < NT) { LOAD_STAGE(kt + 3, (kt + 3) & 3); }
        else             { CP_COMMIT(); }
    }

    // epilogue
    const int g = lane >> 2, t = lane & 3;
    const size_t row_base = (size_t)(bm * 128 + wr);
    const int    col_base = bn * 256 + wc;
#pragma unroll
    for (int mi = 0; mi < 4; mi++) {
#pragma unroll
        for (int nj = 0; nj < 8; nj++) {
            size_t r0 = row_base + mi * 16 + g;
            int    c  = col_base + nj * 8 + t * 2;
            *(float2*)(C + r0 * N + c)       = make_float2(acc[mi][nj][0], acc[mi][nj][1]);
            *(float2*)(C + (r0 + 8) * N + c) = make_float2(acc[mi][nj][2], acc[mi][nj][3]);
        }
    }
}

// =================== bf16 hi/lo split conversions ===========================
// mode 0 (A-operand): [hi, lo, hi]   mode 1 (B-operand): [hi, hi, lo]
__global__ __launch_bounds__(256) void cvt_split(
    const float* __restrict__ src, __nv_bfloat16* __restrict__ dst,
    int C, int total4, int mode)
{
    int i4 = blockIdx.x * 256 + threadIdx.x;
    if (i4 >= total4) return;
    int per_row = C >> 2;
    int r = i4 / per_row, c4 = i4 - r * per_row;
    float4 v = ((const float4*)src)[i4];
    float x[4] = {v.x, v.y, v.z, v.w};
    __nv_bfloat16 h[4], l[4];
#pragma unroll
    for (int i = 0; i < 4; i++) {
        h[i] = __float2bfloat16(x[i]);
        l[i] = __float2bfloat16(x[i] - __bfloat162float(h[i]));
    }
    uint32_t hp0, hp1, lp0, lp1;
    {
        __nv_bfloat162 a = __halves2bfloat162(h[0], h[1]);
        __nv_bfloat162 b = __halves2bfloat162(h[2], h[3]);
        hp0 = *(uint32_t*)&a; hp1 = *(uint32_t*)&b;
        __nv_bfloat162 c = __halves2bfloat162(l[0], l[1]);
        __nv_bfloat162 d = __halves2bfloat162(l[2], l[3]);
        lp0 = *(uint32_t*)&c; lp1 = *(uint32_t*)&d;
    }
    size_t base = (size_t)r * (3 * C) + c4 * 4;
    uint2* d0 = (uint2*)(dst + base);
    uint2* d1 = (uint2*)(dst + base + C);
    uint2* d2 = (uint2*)(dst + base + 2 * C);
    *d0 = make_uint2(hp0, hp1);
    if (mode == 0) { *d1 = make_uint2(lp0, lp1); *d2 = make_uint2(hp0, hp1); }
    else           { *d1 = make_uint2(hp0, hp1); *d2 = make_uint2(lp0, lp1); }
}

// ---------------- ba = hidden @ w_ba^T   ([L,64]) ---------------------------
__global__ __launch_bounds__(256) void ba_kernel(
    const float* __restrict__ hidden, const float* __restrict__ w_ba)
{
    __shared__ __align__(16) float hrow[HDIM];
    __shared__ float red[256];
    const int m = blockIdx.x;
    const int tid = threadIdx.x;
    for (int k = tid; k < HDIM; k += 256) hrow[k] = hidden[(size_t)m * HDIM + k];
    __syncthreads();
    const int n = tid & 63, part = tid >> 6;
    const float4* w4 = (const float4*)(w_ba + (size_t)n * HDIM + part * 512);
    const float4* h4 = (const float4*)(hrow + part * 512);
    float p = 0.f;
#pragma unroll 4
    for (int k = 0; k < 128; k++) {
        float4 a = h4[k], b = w4[k];
        p += a.x * b.x + a.y * b.y + a.z * b.z + a.w * b.w;
    }
    red[tid] = p;
    __syncthreads();
    if (tid < 64)
        g_ba[m * 64 + tid] = red[tid] + red[tid + 64] + red[tid + 128] + red[tid + 192];
}

// ---------------- causal depthwise conv (K=4) + SiLU ------------------------
__global__ __launch_bounds__(256) void conv_kernel(const float* __restrict__ conv_w)
{
    const int t = blockIdx.y;
    const int c = blockIdx.x * 256 + threadIdx.x;
    int col;
    if (c < 2048)       col = (c >> 7) * 768 + (c & 127);
    else if (c < 4096)  { int cc = c - 2048; col = (cc >> 7) * 768 + 128 + (cc & 127); }
    else                { int cc = c - 4096; col = (cc >> 8) * 768 + 256 + (cc & 255); }

    const float4 w = ((const float4*)conv_w)[c];
    float acc = 0.f;
    if (t >= 3) {
        size_t b = (size_t)(t - 3) * QKVZ_N + col;
        acc = g_qkvz[b] * w.x + g_qkvz[b + QKVZ_N] * w.y
            + g_qkvz[b + 2 * QKVZ_N] * w.z + g_qkvz[b + 3 * QKVZ_N] * w.w;
    } else {
        float ws[4] = {w.x, w.y, w.z, w.w};
#pragma unroll
        for (int j = 0; j < 4; j++) {
            int tt = t - 3 + j;
            if (tt >= 0) acc += g_qkvz[(size_t)tt * QKVZ_N + col] * ws[j];
        }
    }
    g_mixed[(size_t)t * MIXED_N + c] = acc / (1.f + expf(-acc));
}

// ---------------- q/k l2norm (+ q scale) ------------------------------------
__global__ __launch_bounds__(128) void prep_kernel()
{
    const int t = blockIdx.y, h = blockIdx.x, tid = threadIdx.x;
    __shared__ float s1[4], s2[4];
    const size_t base = (size_t)t * MIXED_N;
    float qv = g_mixed[base + h * DKD + tid];
    float kv = g_mixed[base + KEY_DIM + h * DKD + tid];
    float a = qv * qv, b = kv * kv;
#pragma unroll
    for (int o = 16; o > 0; o >>= 1) {
        a += __shfl_down_sync(0xffffffffu, a, o);
        b += __shfl_down_sync(0xffffffffu, b, o);
    }
    if ((tid & 31) == 0) { s1[tid >> 5] = a; s2[tid >> 5] = b; }
    __syncthreads();
    float qs = s1[0] + s1[1] + s1[2] + s1[3];
    float ks = s2[0] + s2[1] + s2[2] + s2[3];
    const size_t o = ((size_t)t * NKH + h) * DKD + tid;
    g_qn[o] = qv * rsqrtf(qs + 1e-6f) * 0.08838834764831845f;
    g_kn[o] = kv * rsqrtf(ks + 1e-6f);
}

// ---------------- gates ------------------------------------------------------
__global__ __launch_bounds__(256) void gb_kernel(
    const float* __restrict__ dt_bias, const float* __restrict__ a_log)
{
    const int idx = blockIdx.x * 256 + threadIdx.x;
    const int vh = idx & 31;
    const int t  = idx >> 5;
    const int h  = vh >> 1, i = vh & 1;
    float b = g_ba[t * 64 + h * 4 + i];
    float a = g_ba[t * 64 + h * 4 + 2 + i];
    g_bv[idx] = 1.f / (1.f + expf(-b));
    float x = a + dt_bias[vh];
    float sp = (x > 20.f) ? x : log1pf(expf(x));
    g_gv[idx] = -expf(a_log[vh]) * sp;
}

// ---------------- sequential delta-rule scan (with register prefetch) -------
__global__ __launch_bounds__(128) void scan_kernel()
{
    const int head = blockIdx.y;
    const int vs   = blockIdx.x;
    const int tid  = threadIdx.x;
    const int v    = tid & 31;
    const int kq   = tid >> 5;
    const int kh   = head >> 1;

    __shared__ __align__(16) float ks[128];
    __shared__ __align__(16) float qs[128];
    __shared__ float vsm[32];
    __shared__ float red[4][32];
    __shared__ float red2[4][32];

    float s[32];
#pragma unroll
    for (int i = 0; i < 32; i++) s[i] = 0.f;
    float ksr[32];

    const int vcol = head * DVD + vs * 32;

    // prefetch t=0
    size_t kb = (size_t)kh * DKD;
    float pk = g_kn[kb + tid];
    float pq = g_qn[kb + tid];
    float pv = (tid < 32) ? g_mixed[(size_t)KEY_DIM * 2 + vcol + tid] : 0.f;
    float pg = g_gv[head];
    float pb = g_bv[head];

    for (int t = 0; t < LSEQ; t++) {
        ks[tid] = pk;
        qs[tid] = pq;
        if (tid < 32) vsm[tid] = pv;
        const float gt = pg;
        const float bt = pb;
        __syncthreads();

        // prefetch t+1 (overlaps compute below)
        if (t + 1 < LSEQ) {
            const size_t kb1 = ((size_t)(t + 1) * NKH + kh) * DKD;
            pk = g_kn[kb1 + tid];
            pq = g_qn[kb1 + tid];
            if (tid < 32) pv = g_mixed[(size_t)(t + 1) * MIXED_N + KEY_DIM * 2 + vcol + tid];
            pg = g_gv[(t + 1) * NVH + head];
            pb = g_bv[(t + 1) * NVH + head];
        }

        const float4* k4 = (const float4*)(ks + kq * 32);
        float p = 0.f;
#pragma unroll
        for (int i = 0; i < 8; i++) {
            float4 kk = k4[i];
            ksr[4*i+0] = kk.x; ksr[4*i+1] = kk.y; ksr[4*i+2] = kk.z; ksr[4*i+3] = kk.w;
            p += s[4*i+0]*kk.x + s[4*i+1]*kk.y + s[4*i+2]*kk.z + s[4*i+3]*kk.w;
        }
        red[kq][v] = p;
        __syncthreads();

        const float eg = expf(gt);
        const float kvsum = red[0][v] + red[1][v] + red[2][v] + red[3][v];
        const float delta = (vsm[v] - eg * kvsum) * bt;

        const float4* q4 = (const float4*)(qs + kq * 32);
        float op = 0.f;
#pragma unroll
        for (int i = 0; i < 8; i++) {
            float4 qq = q4[i];
            float s0 = eg * s[4*i+0] + ksr[4*i+0] * delta; s[4*i+0] = s0; op += s0 * qq.x;
            float s1 = eg * s[4*i+1] + ksr[4*i+1] * delta; s[4*i+1] = s1; op += s1 * qq.y;
            float s2 = eg * s[4*i+2] + ksr[4*i+2] * delta; s[4*i+2] = s2; op += s2 * qq.z;
            float s3 = eg * s[4*i+3] + ksr[4*i+3] * delta; s[4*i+3] = s3; op += s3 * qq.w;
        }
        red2[kq][v] = op;
        __syncthreads();

        if (kq == 0) {
            float o = red2[0][v] + red2[1][v] + red2[2][v] + red2[3][v];
            g_core[(size_t)t * VAL_DIM + vcol + v] = o;
        }
    }
}

// ---------------- RMSNorm + gate; writes bf16 [hi,lo,hi] for GEMM2 ----------
__global__ __launch_bounds__(128) void gate_kernel(const float* __restrict__ norm_w)
{
    const int t = blockIdx.y, vh = blockIdx.x, tid = threadIdx.x;
    __shared__ float sm[4];
    const size_t ci = (size_t)t * VAL_DIM + vh * DVD + tid;
    float c = g_core[ci];
    float ss = c * c;
#pragma unroll
    for (int o = 16; o > 0; o >>= 1) ss += __shfl_down_sync(0xffffffffu, ss, o);
    if ((tid & 31) == 0) sm[tid >> 5] = ss;
    __syncthreads();
    float sum = sm[0] + sm[1] + sm[2] + sm[3];
    float r = rsqrtf(sum * (1.0f / 128.0f) + 1e-6f);
    float z = g_qkvz[(size_t)t * QKVZ_N + (vh >> 1) * 768 + 512 + (vh & 1) * 128 + tid];
    float sz = z / (1.f + expf(-z));
    float x = c * r * norm_w[tid] * sz;

    __nv_bfloat16 hi = __float2bfloat16(x);
    __nv_bfloat16 lo = __float2bfloat16(x - __bfloat162float(hi));
    const size_t rb = (size_t)t * KP2;
    const int col = vh * DVD + tid;
    g_a2[rb + col]                = hi;
    g_a2[rb + VAL_DIM + col]      = lo;
    g_a2[rb + 2 * VAL_DIM + col]  = hi;
}

// ---------------- launch ------------------------------------------------------
extern "C" void kernel_launch(void* const* d_in, const int* in_sizes, int n_in,
                              void* d_out, int out_size)
{
    const float* hidden  = (const float*)d_in[0];
    const float* w_qkvz  = (const float*)d_in[1];
    const float* w_ba    = (const float*)d_in[2];
    const float* conv_w  = (const float*)d_in[3];
    const float* dt_bias = (const float*)d_in[4];
    const float* a_log   = (const float*)d_in[5];
    const float* norm_w  = (const float*)d_in[6];
    const float* w_out   = (const float*)d_in[7];
    float* out = (float*)d_out;

    float *p_qkvz = nullptr;
    __nv_bfloat16 *p_a1, *p_b1, *p_a2, *p_b2;
    cudaGetSymbolAddress((void**)&p_qkvz, g_qkvz);
    cudaGetSymbolAddress((void**)&p_a1, g_a1);
    cudaGetSymbolAddress((void**)&p_b1, g_b1);
    cudaGetSymbolAddress((void**)&p_a2, g_a2);
    cudaGetSymbolAddress((void**)&p_b2, g_b2);

    cudaFuncSetAttribute(mma_gemm, cudaFuncAttributeMaxDynamicSharedMemorySize, GEMM_SMEM);

    // split conversions for GEMM1 operands + GEMM2 B operand
    { int t4 = (LSEQ * HDIM) / 4;    cvt_split<<<(t4 + 255) / 256, 256>>>(hidden, p_a1, HDIM, t4, 0); }
    { int t4 = (QKVZ_N * HDIM) / 4;  cvt_split<<<(t4 + 255) / 256, 256>>>(w_qkvz, p_b1, HDIM, t4, 1); }
    { int t4 = (HDIM * VAL_DIM) / 4; cvt_split<<<(t4 + 255) / 256, 256>>>(w_out,  p_b2, VAL_DIM, t4, 1); }

    // 1) qkvz = hidden @ w_qkvz^T  (bf16 mma.sync, 3-term split)
    mma_gemm<<<dim3(QKVZ_N / 256, LSEQ / 128), 256, GEMM_SMEM>>>(p_a1, p_b1, p_qkvz, QKVZ_N, KP1);
    // 2) ba
    ba_kernel<<<LSEQ, 256>>>(hidden, w_ba);
    // 3) conv + silu
    conv_kernel<<<dim3(MIXED_N / 256, LSEQ), 256>>>(conv_w);
    // 4) l2norm q,k
    prep_kernel<<<dim3(NKH, LSEQ), 128>>>();
    // 5) gates
    gb_kernel<<<(LSEQ * NVH) / 256, 256>>>(dt_bias, a_log);
    // 6) scan
    scan_kernel<<<dim3(4, NVH), 128>>>();
    // 7) rmsnorm + gate (emits bf16 split operand)
    gate_kernel<<<dim3(NVH, LSEQ), 128>>>(norm_w);
    // 8) out = gated @ w_out^T (bf16 mma.sync)
    mma_gemm<<<dim3(HDIM / 256, LSEQ / 128), 256, GEMM_SMEM>>>(p_a2, p_b2, out, HDIM, KP2);
}